// round 11
// baseline (speedup 1.0000x reference)
#include <cuda_runtime.h>
#include <math.h>
#include <stdint.h>

#define B_  8
#define T_  8192
#define F_  64
#define M_  128          // omega rows
#define MM2 256          // feature dim = 2*M
#define D_  64
#define DP_ 65           // D + 1 (normalizer column)

#define KV_CH    37      // grid 37*8 = 296 = one wave at 2 CTA/SM
#define KV_ROWS  224     // rows per chunk (37*224 = 8288 >= 8192, tail masked)

constexpr float kEPS   = 1e-9f;
constexpr float kSCALE = 0.0625f;  // 1/sqrt(2*128) = 1/16

typedef unsigned long long ull;

// ---------------- packed f32x2 helpers (Blackwell) ----------------
__device__ __forceinline__ ull pack2(float a, float b) {
    ull r; asm("mov.b64 %0, {%1,%2};" : "=l"(r) : "f"(a), "f"(b)); return r;
}
__device__ __forceinline__ void unpack2(ull v, float& lo, float& hi) {
    asm("mov.b64 {%0,%1}, %2;" : "=f"(lo), "=f"(hi) : "l"(v));
}
__device__ __forceinline__ ull fma2(ull a, ull b, ull c) {
    ull d; asm("fma.rn.f32x2 %0, %1, %2, %3;" : "=l"(d) : "l"(a), "l"(b), "l"(c)); return d;
}

// ---------------- device scratch (static, allocation-free) ----------------
// d-major partials: g_kvp[((cx*B+b)*DP + d)*MM2 + m]
__device__ float g_kvp[(size_t)KV_CH * B_ * DP_ * MM2];    // 19.7 MB
__device__ float g_kv [(size_t)B_ * DP_ * MM2];            // 0.53 MB

// ======================= Stage 1: kv_fused (phi_k + kv) =======================
// grid (KV_CH, B), block 512, 2 CTA/SM. Per 32-row step:
//   stage K/V -> phi GEMM (scalar, R9-identical) -> packed-f32x2 accumulate
//   (thread = 4m x 8d tile; V pairs straight off LDS.128, only phi splatted).
#define KVF_WT   0                         // [64][132] omega^T padded
#define KVF_XS   (64 * 132)                // [32][68]
#define KVF_VS   (KVF_XS + 32 * 68)        // [32][68]
#define KVF_PHI  (KVF_VS + 32 * 68)        // [32][260]
#define KVF_SS   (KVF_PHI + 32 * 260)      // [32]
#define KVF_SMEM ((KVF_SS + 32) * 4)       // 84,608 B -> x2 = 169 KB/SM

__global__ void __launch_bounds__(512, 2) kv_fused(const float* __restrict__ key,
                                                   const float* __restrict__ value,
                                                   const float* __restrict__ omega)
{
    extern __shared__ float sm[];
    float* wT   = sm + KVF_WT;
    float* xs   = sm + KVF_XS;
    float* vs   = sm + KVF_VS;
    float* phis = sm + KVF_PHI;
    float* ss   = sm + KVF_SS;

    const int b   = blockIdx.y;
    const int cx  = blockIdx.x;
    const int s0  = cx * KV_ROWS;
    const int tid = threadIdx.x;

    // load omega transposed: wT[f][m], stride 132 (one-time)
    #pragma unroll
    for (int i = 0; i < 16; i++) {
        int idx = tid + 512 * i;               // 8192 floats, omega[m][f]
        wT[(idx & 63) * 132 + (idx >> 6)] = omega[idx];
    }

    // ---- roles ----
    const int wid = tid >> 5;      // warp 0..15: phi rows wid*2, wid*2+1
    const int tx  = tid & 31;      // phi m-quad
    const int lr  = tid >> 4;      // staging row 0..31
    const int lc  = tid & 15;      // staging float4 col
    const int mi  = tid & 63;      // accumulate m-quad (m = mi*4)
    const int di  = tid >> 6;      // accumulate d-octet (d = di*8)

    // packed register tile: a2[mm][dp] = (d = di*8 + 2*dp, +1) for m = mi*4+mm
    ull a2[4][4];
    #pragma unroll
    for (int mm = 0; mm < 4; mm++)
        #pragma unroll
        for (int dp = 0; dp < 4; dp++) a2[mm][dp] = 0ULL;
    float4 accn = make_float4(0.f, 0.f, 0.f, 0.f);   // used by di==0 threads

    for (int sb = 0; sb < KV_ROWS; sb += 32) {
        const int sg = s0 + sb;
        __syncthreads();                       // prev accumulate done

        // ---- stage 32 key + 32 value rows; ss via 16-lane shfl ----
        {
            const int r = sg + lr;
            float4 xv = make_float4(0.f, 0.f, 0.f, 0.f);
            float4 vv = make_float4(0.f, 0.f, 0.f, 0.f);
            if (r < T_) {
                xv = *reinterpret_cast<const float4*>(key   + ((size_t)b * T_ + r) * F_ + lc * 4);
                vv = *reinterpret_cast<const float4*>(value + ((size_t)b * T_ + r) * D_ + lc * 4);
            }
            *reinterpret_cast<float4*>(&xs[lr * 68 + lc * 4]) = xv;
            *reinterpret_cast<float4*>(&vs[lr * 68 + lc * 4]) = vv;
            float p = xv.x * xv.x + xv.y * xv.y + xv.z * xv.z + xv.w * xv.w;
            p += __shfl_xor_sync(0xffffffffu, p, 8);
            p += __shfl_xor_sync(0xffffffffu, p, 4);
            p += __shfl_xor_sync(0xffffffffu, p, 2);
            p += __shfl_xor_sync(0xffffffffu, p, 1);
            if (lc == 0) ss[lr] = 0.5f * p;
        }
        __syncthreads();

        // ---- phi GEMM (scalar, R9-identical): warp wid -> rows wid*2..+1 ----
        {
            float a[2][4];
            #pragma unroll
            for (int jp = 0; jp < 2; jp++)
                #pragma unroll
                for (int c = 0; c < 4; c++) a[jp][c] = 0.f;

            #pragma unroll
            for (int f0 = 0; f0 < 64; f0 += 4) {
                float4 w0 = *reinterpret_cast<const float4*>(&wT[(f0 + 0) * 132 + tx * 4]);
                float4 w1 = *reinterpret_cast<const float4*>(&wT[(f0 + 1) * 132 + tx * 4]);
                float4 w2 = *reinterpret_cast<const float4*>(&wT[(f0 + 2) * 132 + tx * 4]);
                float4 w3 = *reinterpret_cast<const float4*>(&wT[(f0 + 3) * 132 + tx * 4]);
                #pragma unroll
                for (int jp = 0; jp < 2; jp++) {
                    float4 xv = *reinterpret_cast<const float4*>(&xs[(wid * 2 + jp) * 68 + f0]);
                    a[jp][0] += xv.x * w0.x + xv.y * w1.x + xv.z * w2.x + xv.w * w3.x;
                    a[jp][1] += xv.x * w0.y + xv.y * w1.y + xv.z * w2.y + xv.w * w3.y;
                    a[jp][2] += xv.x * w0.z + xv.y * w1.z + xv.z * w2.z + xv.w * w3.z;
                    a[jp][3] += xv.x * w0.w + xv.y * w1.w + xv.z * w2.w + xv.w * w3.w;
                }
            }
            #pragma unroll
            for (int jp = 0; jp < 2; jp++) {
                int r = wid * 2 + jp;
                float s  = ss[r];
                float sc = (sg + r < T_) ? kSCALE : 0.f;
                float4 p1, p2;
                p1.x = (__expf( a[jp][0] - s) + kEPS) * sc;
                p1.y = (__expf( a[jp][1] - s) + kEPS) * sc;
                p1.z = (__expf( a[jp][2] - s) + kEPS) * sc;
                p1.w = (__expf( a[jp][3] - s) + kEPS) * sc;
                p2.x = (__expf(-a[jp][0] - s) + kEPS) * sc;
                p2.y = (__expf(-a[jp][1] - s) + kEPS) * sc;
                p2.z = (__expf(-a[jp][2] - s) + kEPS) * sc;
                p2.w = (__expf(-a[jp][3] - s) + kEPS) * sc;
                *reinterpret_cast<float4*>(&phis[r * 260 + tx * 4])       = p1;
                *reinterpret_cast<float4*>(&phis[r * 260 + 128 + tx * 4]) = p2;
            }
        }
        __syncthreads();

        // ---- packed accumulate: 3 LDS + 4 splats + 16 FFMA2 per j ----
        #pragma unroll 4
        for (int j = 0; j < 32; j++) {
            float4 ph = *reinterpret_cast<const float4*>(&phis[j * 260 + mi * 4]);   // conflict-free
            ulonglong2 va = *reinterpret_cast<const ulonglong2*>(&vs[j * 68 + di * 8]);      // broadcast
            ulonglong2 vb = *reinterpret_cast<const ulonglong2*>(&vs[j * 68 + di * 8 + 4]);  // broadcast
            ull s0 = pack2(ph.x, ph.x);
            ull s1 = pack2(ph.y, ph.y);
            ull s2 = pack2(ph.z, ph.z);
            ull s3 = pack2(ph.w, ph.w);
            a2[0][0] = fma2(s0, va.x, a2[0][0]); a2[0][1] = fma2(s0, va.y, a2[0][1]);
            a2[0][2] = fma2(s0, vb.x, a2[0][2]); a2[0][3] = fma2(s0, vb.y, a2[0][3]);
            a2[1][0] = fma2(s1, va.x, a2[1][0]); a2[1][1] = fma2(s1, va.y, a2[1][1]);
            a2[1][2] = fma2(s1, vb.x, a2[1][2]); a2[1][3] = fma2(s1, vb.y, a2[1][3]);
            a2[2][0] = fma2(s2, va.x, a2[2][0]); a2[2][1] = fma2(s2, va.y, a2[2][1]);
            a2[2][2] = fma2(s2, vb.x, a2[2][2]); a2[2][3] = fma2(s2, vb.y, a2[2][3]);
            a2[3][0] = fma2(s3, va.x, a2[3][0]); a2[3][1] = fma2(s3, va.y, a2[3][1]);
            a2[3][2] = fma2(s3, vb.x, a2[3][2]); a2[3][3] = fma2(s3, vb.y, a2[3][3]);
            if (di == 0) {
                accn.x += ph.x; accn.y += ph.y; accn.z += ph.z; accn.w += ph.w;
            }
        }
    }

    // ---- unpack and store d-major partials (coalesced float4 over m) ----
    const size_t slab = (size_t)(cx * B_ + b) * DP_;
    #pragma unroll
    for (int dp = 0; dp < 4; dp++) {
        float lo0, hi0, lo1, hi1, lo2, hi2, lo3, hi3;
        unpack2(a2[0][dp], lo0, hi0);
        unpack2(a2[1][dp], lo1, hi1);
        unpack2(a2[2][dp], lo2, hi2);
        unpack2(a2[3][dp], lo3, hi3);
        float4 e = make_float4(lo0, lo1, lo2, lo3);   // d = di*8 + 2*dp
        float4 o = make_float4(hi0, hi1, hi2, hi3);   // d = di*8 + 2*dp + 1
        *reinterpret_cast<float4*>(&g_kvp[(slab + di * 8 + 2 * dp)     * MM2 + mi * 4]) = e;
        *reinterpret_cast<float4*>(&g_kvp[(slab + di * 8 + 2 * dp + 1) * MM2 + mi * 4]) = o;
    }
    if (di == 0)
        *reinterpret_cast<float4*>(&g_kvp[(slab + 64) * MM2 + mi * 4]) = accn;
}

// ======================= Stage 2: reduce partials (float4) =======================
#define KV_N4 (B_ * DP_ * MM2 / 4)   // 33280

__global__ void __launch_bounds__(256) reduce_kv()
{
    int i = blockIdx.x * blockDim.x + threadIdx.x;
    if (i < KV_N4) {
        const float4* src = reinterpret_cast<const float4*>(g_kvp);
        float4 s = make_float4(0.f, 0.f, 0.f, 0.f);
        #pragma unroll
        for (int c = 0; c < KV_CH; c++) {
            float4 v = src[(size_t)c * KV_N4 + i];
            s.x += v.x; s.y += v.y; s.z += v.z; s.w += v.w;
        }
        reinterpret_cast<float4*>(g_kv)[i] = s;
    }
}

// ======================= Stage 3: qkv_fused (phi_q + qkv + normalize) =======================
// grid (T/64, B), block 256. Phase A scalar (R9-identical). Phase B packed:
// thread = 4r x 4c tile, 2 LDS + 4 splats + 8 FFMA2 per m.
#define QF_KVS  0                          // [256][68]  kv[m][d]
#define QF_WT   (256 * 68)                 // [64][132]
#define QF_XS   (QF_WT + 64 * 132)         // [64][68]
#define QF_PHT  (QF_XS + 64 * 68)          // [256][68]  phi^T[m][r]
#define QF_SS   (QF_PHT + 256 * 68)        // [64]
#define QF_NRM  (QF_SS + 64)               // [64]
#define QF_SMEM ((QF_NRM + 64) * 4)        // 190,976 B

__global__ void __launch_bounds__(256) qkv_fused(const float* __restrict__ query,
                                                 const float* __restrict__ omega,
                                                 float* __restrict__ out)
{
    extern __shared__ float sm[];
    float* kvs   = sm + QF_KVS;
    float* wT    = sm + QF_WT;
    float* xs    = sm + QF_XS;
    float* phisT = sm + QF_PHT;
    float* ss    = sm + QF_SS;
    float* norm  = sm + QF_NRM;

    const int b    = blockIdx.y;
    const int t0   = blockIdx.x * 64;
    const int tid  = threadIdx.x;
    const int wid  = tid >> 5;     // 0..7 -> m-16-group
    const int lane = tid & 31;

    // ---- loads: kv (d-major -> [m][d]), omega^T, query tile ----
    {
        const float* kvg = g_kv + (size_t)b * DP_ * MM2;
        #pragma unroll
        for (int it = 0; it < 65; it++) {
            int i = tid + 256 * it;                 // 16640 floats
            int d = i >> 8, mm = i & 255;
            kvs[mm * 68 + d] = kvg[i];
        }
        #pragma unroll
        for (int i = 0; i < 32; i++) {
            int idx = tid + 256 * i;
            wT[(idx & 63) * 132 + (idx >> 6)] = omega[idx];
        }
        const float4* xg = reinterpret_cast<const float4*>(query + ((size_t)b * T_ + t0) * F_);
        #pragma unroll
        for (int i = 0; i < 4; i++) {
            int idx = tid + 256 * i;                // 1024 float4
            int r = idx >> 4, c4 = idx & 15;
            *reinterpret_cast<float4*>(&xs[r * 68 + c4 * 4]) = xg[idx];
        }
    }
    __syncthreads();

    // ---- ss[r] = 0.5 * ||x_r||^2 ----
    if (tid < 64) {
        float p = 0.f;
        #pragma unroll
        for (int f = 0; f < 64; f++) { float v = xs[tid * 68 + f]; p += v * v; }
        ss[tid] = 0.5f * p;
    }
    __syncthreads();

    // ---- phase A: phi_q GEMM (scalar, R9-identical) ----
    {
        float a[2][16];
        #pragma unroll
        for (int jp = 0; jp < 2; jp++)
            #pragma unroll
            for (int c = 0; c < 16; c++) a[jp][c] = 0.f;

        const float* xr0 = &xs[lane * 68];
        const float* xr1 = &xs[(lane + 32) * 68];
        #pragma unroll 4
        for (int f0 = 0; f0 < 64; f0 += 4) {
            float4 xv0 = *reinterpret_cast<const float4*>(&xr0[f0]);
            float4 xv1 = *reinterpret_cast<const float4*>(&xr1[f0]);
            #pragma unroll
            for (int i = 0; i < 4; i++) {
                const float* wr = &wT[(f0 + i) * 132 + wid * 16];
                float4 wa = *reinterpret_cast<const float4*>(wr);
                float4 wb = *reinterpret_cast<const float4*>(wr + 4);
                float4 wc = *reinterpret_cast<const float4*>(wr + 8);
                float4 wd = *reinterpret_cast<const float4*>(wr + 12);
                float x0 = (i == 0) ? xv0.x : (i == 1) ? xv0.y : (i == 2) ? xv0.z : xv0.w;
                float x1 = (i == 0) ? xv1.x : (i == 1) ? xv1.y : (i == 2) ? xv1.z : xv1.w;
                a[0][0]  += x0 * wa.x; a[0][1]  += x0 * wa.y; a[0][2]  += x0 * wa.z; a[0][3]  += x0 * wa.w;
                a[0][4]  += x0 * wb.x; a[0][5]  += x0 * wb.y; a[0][6]  += x0 * wb.z; a[0][7]  += x0 * wb.w;
                a[0][8]  += x0 * wc.x; a[0][9]  += x0 * wc.y; a[0][10] += x0 * wc.z; a[0][11] += x0 * wc.w;
                a[0][12] += x0 * wd.x; a[0][13] += x0 * wd.y; a[0][14] += x0 * wd.z; a[0][15] += x0 * wd.w;
                a[1][0]  += x1 * wa.x; a[1][1]  += x1 * wa.y; a[1][2]  += x1 * wa.z; a[1][3]  += x1 * wa.w;
                a[1][4]  += x1 * wb.x; a[1][5]  += x1 * wb.y; a[1][6]  += x1 * wb.z; a[1][7]  += x1 * wb.w;
                a[1][8]  += x1 * wc.x; a[1][9]  += x1 * wc.y; a[1][10] += x1 * wc.z; a[1][11] += x1 * wc.w;
                a[1][12] += x1 * wd.x; a[1][13] += x1 * wd.y; a[1][14] += x1 * wd.z; a[1][15] += x1 * wd.w;
            }
        }

        // exp + transposed store: phisT[m][r], lane = r -> conflict-free STS.32
        #pragma unroll
        for (int jp = 0; jp < 2; jp++) {
            int r = lane + jp * 32;
            float s = ss[r];
            #pragma unroll
            for (int c = 0; c < 16; c++) {
                int m = wid * 16 + c;
                phisT[m * 68 + r]         = (__expf( a[jp][c] - s) + kEPS) * kSCALE;
                phisT[(128 + m) * 68 + r] = (__expf(-a[jp][c] - s) + kEPS) * kSCALE;
            }
        }
    }
    __syncthreads();

    // ---- phase B: out = phi_q @ kv; packed f32x2, thread = 4 rows x 4 cols ----
    const int rg = tid & 15;       // rows rg*4..rg*4+3
    const int cg = tid >> 4;       // cols cg*4..cg*4+3

    ull a2[4][2];                  // [row][colpair]
    #pragma unroll
    for (int rr = 0; rr < 4; rr++) { a2[rr][0] = 0ULL; a2[rr][1] = 0ULL; }
    float4 anorm = make_float4(0.f, 0.f, 0.f, 0.f);

    #pragma unroll 4
    for (int m = 0; m < MM2; m++) {
        float4 ph = *reinterpret_cast<const float4*>(&phisT[m * 68 + rg * 4]);  // conflict-free
        ulonglong2 kv2 = *reinterpret_cast<const ulonglong2*>(&kvs[m * 68 + cg * 4]);  // ~broadcast
        ull s0 = pack2(ph.x, ph.x);
        ull s1 = pack2(ph.y, ph.y);
        ull s2 = pack2(ph.z, ph.z);
        ull s3 = pack2(ph.w, ph.w);
        a2[0][0] = fma2(s0, kv2.x, a2[0][0]); a2[0][1] = fma2(s0, kv2.y, a2[0][1]);
        a2[1][0] = fma2(s1, kv2.x, a2[1][0]); a2[1][1] = fma2(s1, kv2.y, a2[1][1]);
        a2[2][0] = fma2(s2, kv2.x, a2[2][0]); a2[2][1] = fma2(s2, kv2.y, a2[2][1]);
        a2[3][0] = fma2(s3, kv2.x, a2[3][0]); a2[3][1] = fma2(s3, kv2.y, a2[3][1]);
        if (cg == 0) {
            float kn = kvs[m * 68 + 64];
            anorm.x += ph.x * kn; anorm.y += ph.y * kn;
            anorm.z += ph.z * kn; anorm.w += ph.w * kn;
        }
    }

    if (cg == 0) {
        norm[rg * 4 + 0] = anorm.x;
        norm[rg * 4 + 1] = anorm.y;
        norm[rg * 4 + 2] = anorm.z;
        norm[rg * 4 + 3] = anorm.w;
    }
    __syncthreads();

    #pragma unroll
    for (int rr = 0; rr < 4; rr++) {
        float inv = 1.0f / norm[rg * 4 + rr];
        float c0, c1, c2, c3;
        unpack2(a2[rr][0], c0, c1);
        unpack2(a2[rr][1], c2, c3);
        float4 o = make_float4(c0 * inv, c1 * inv, c2 * inv, c3 * inv);
        *reinterpret_cast<float4*>(out + ((size_t)b * T_ + t0 + rg * 4 + rr) * D_ + cg * 4) = o;
    }
}

// ======================= launch =======================
extern "C" void kernel_launch(void* const* d_in, const int* in_sizes, int n_in,
                              void* d_out, int out_size)
{
    const float* query = (const float*)d_in[0];
    const float* value = (const float*)d_in[1];
    const float* key   = (const float*)d_in[2];
    const float* omega = (const float*)d_in[3];
    float* out = (float*)d_out;

    cudaFuncSetAttribute(kv_fused,  cudaFuncAttributeMaxDynamicSharedMemorySize, KVF_SMEM);
    cudaFuncSetAttribute(qkv_fused, cudaFuncAttributeMaxDynamicSharedMemorySize, QF_SMEM);

    dim3 gkv(KV_CH, B_);
    kv_fused<<<gkv, 512, KVF_SMEM>>>(key, value, omega);
    reduce_kv<<<(KV_N4 + 255) / 256, 256>>>();

    dim3 gq(T_ / 64, B_);
    qkv_fused<<<gq, 256, QF_SMEM>>>(query, omega, out);
}

// round 13
// speedup vs baseline: 1.6262x; 1.6262x over previous
#include <cuda_runtime.h>
#include <math.h>
#include <stdint.h>

#define B_  8
#define T_  8192
#define F_  64
#define M_  128          // omega rows
#define MM2 256          // feature dim = 2*M
#define D_  64
#define DP_ 65           // D + 1 (normalizer column)

#define KV_CH    37      // grid 37*8 = 296 = one wave at 2 CTA/SM
#define KV_ROWS  224     // rows per chunk (37*224 = 8288 >= 8192, tail masked)

constexpr float kEPS   = 1e-9f;
constexpr float kSCALE = 0.0625f;  // 1/sqrt(2*128) = 1/16

typedef unsigned long long ull;

// ---------------- packed f32x2 helpers (Blackwell) ----------------
__device__ __forceinline__ ull pack2(float a, float b) {
    ull r; asm("mov.b64 %0, {%1,%2};" : "=l"(r) : "f"(a), "f"(b)); return r;
}
__device__ __forceinline__ void unpack2(ull v, float& lo, float& hi) {
    asm("mov.b64 {%0,%1}, %2;" : "=f"(lo), "=f"(hi) : "l"(v));
}
__device__ __forceinline__ ull fma2(ull a, ull b, ull c) {
    ull d; asm("fma.rn.f32x2 %0, %1, %2, %3;" : "=l"(d) : "l"(a), "l"(b), "l"(c)); return d;
}

// ---------------- device scratch (static, allocation-free) ----------------
// d-major partials: g_kvp[((cx*B+b)*DP + d)*MM2 + m]
__device__ float g_kvp[(size_t)KV_CH * B_ * DP_ * MM2];    // 19.7 MB
__device__ float g_kv [(size_t)B_ * DP_ * MM2];            // 0.53 MB

// ======================= Stage 1: kv_fused (phi_k + kv) =======================
// grid (KV_CH, B), block 512, 2 CTA/SM. Per 32-row step:
//   stage K/V -> phi GEMM (scalar, R9-identical) -> packed-f32x2 accumulate
//   (thread = 4m x 8d tile; V pairs straight off LDS.128, only phi splatted).
#define KVF_WT   0                         // [64][132] omega^T padded
#define KVF_XS   (64 * 132)                // [32][68]
#define KVF_VS   (KVF_XS + 32 * 68)        // [32][68]
#define KVF_PHI  (KVF_VS + 32 * 68)        // [32][260]
#define KVF_SS   (KVF_PHI + 32 * 260)      // [32]
#define KVF_SMEM ((KVF_SS + 32) * 4)       // 84,608 B -> x2 = 169 KB/SM

__global__ void __launch_bounds__(512, 2) kv_fused(const float* __restrict__ key,
                                                   const float* __restrict__ value,
                                                   const float* __restrict__ omega)
{
    extern __shared__ float sm[];
    float* wT   = sm + KVF_WT;
    float* xs   = sm + KVF_XS;
    float* vs   = sm + KVF_VS;
    float* phis = sm + KVF_PHI;
    float* ss   = sm + KVF_SS;

    const int b   = blockIdx.y;
    const int cx  = blockIdx.x;
    const int s0  = cx * KV_ROWS;
    const int tid = threadIdx.x;

    // load omega transposed: wT[f][m], stride 132 (one-time)
    #pragma unroll
    for (int i = 0; i < 16; i++) {
        int idx = tid + 512 * i;               // 8192 floats, omega[m][f]
        wT[(idx & 63) * 132 + (idx >> 6)] = omega[idx];
    }

    // ---- roles ----
    const int wid = tid >> 5;      // warp 0..15: phi rows wid*2, wid*2+1
    const int tx  = tid & 31;      // phi m-quad
    const int lr  = tid >> 4;      // staging row 0..31
    const int lc  = tid & 15;      // staging float4 col
    const int mi  = tid & 63;      // accumulate m-quad (m = mi*4)
    const int di  = tid >> 6;      // accumulate d-octet (d = di*8)

    // packed register tile: a2[mm][dp] = (d = di*8 + 2*dp, +1) for m = mi*4+mm
    ull a2[4][4];
    #pragma unroll
    for (int mm = 0; mm < 4; mm++)
        #pragma unroll
        for (int dp = 0; dp < 4; dp++) a2[mm][dp] = 0ULL;
    float4 accn = make_float4(0.f, 0.f, 0.f, 0.f);   // used by di==0 threads

    for (int sb = 0; sb < KV_ROWS; sb += 32) {
        const int sg = s0 + sb;
        __syncthreads();                       // prev accumulate done

        // ---- stage 32 key + 32 value rows; ss via 16-lane shfl ----
        {
            const int r = sg + lr;
            float4 xv = make_float4(0.f, 0.f, 0.f, 0.f);
            float4 vv = make_float4(0.f, 0.f, 0.f, 0.f);
            if (r < T_) {
                xv = *reinterpret_cast<const float4*>(key   + ((size_t)b * T_ + r) * F_ + lc * 4);
                vv = *reinterpret_cast<const float4*>(value + ((size_t)b * T_ + r) * D_ + lc * 4);
            }
            *reinterpret_cast<float4*>(&xs[lr * 68 + lc * 4]) = xv;
            *reinterpret_cast<float4*>(&vs[lr * 68 + lc * 4]) = vv;
            float p = xv.x * xv.x + xv.y * xv.y + xv.z * xv.z + xv.w * xv.w;
            p += __shfl_xor_sync(0xffffffffu, p, 8);
            p += __shfl_xor_sync(0xffffffffu, p, 4);
            p += __shfl_xor_sync(0xffffffffu, p, 2);
            p += __shfl_xor_sync(0xffffffffu, p, 1);
            if (lc == 0) ss[lr] = 0.5f * p;
        }
        __syncthreads();

        // ---- phi GEMM (scalar, R9-identical): warp wid -> rows wid*2..+1 ----
        {
            float a[2][4];
            #pragma unroll
            for (int jp = 0; jp < 2; jp++)
                #pragma unroll
                for (int c = 0; c < 4; c++) a[jp][c] = 0.f;

            #pragma unroll
            for (int f0 = 0; f0 < 64; f0 += 4) {
                float4 w0 = *reinterpret_cast<const float4*>(&wT[(f0 + 0) * 132 + tx * 4]);
                float4 w1 = *reinterpret_cast<const float4*>(&wT[(f0 + 1) * 132 + tx * 4]);
                float4 w2 = *reinterpret_cast<const float4*>(&wT[(f0 + 2) * 132 + tx * 4]);
                float4 w3 = *reinterpret_cast<const float4*>(&wT[(f0 + 3) * 132 + tx * 4]);
                #pragma unroll
                for (int jp = 0; jp < 2; jp++) {
                    float4 xv = *reinterpret_cast<const float4*>(&xs[(wid * 2 + jp) * 68 + f0]);
                    a[jp][0] += xv.x * w0.x + xv.y * w1.x + xv.z * w2.x + xv.w * w3.x;
                    a[jp][1] += xv.x * w0.y + xv.y * w1.y + xv.z * w2.y + xv.w * w3.y;
                    a[jp][2] += xv.x * w0.z + xv.y * w1.z + xv.z * w2.z + xv.w * w3.z;
                    a[jp][3] += xv.x * w0.w + xv.y * w1.w + xv.z * w2.w + xv.w * w3.w;
                }
            }
            #pragma unroll
            for (int jp = 0; jp < 2; jp++) {
                int r = wid * 2 + jp;
                float s  = ss[r];
                float sc = (sg + r < T_) ? kSCALE : 0.f;
                float4 p1, p2;
                p1.x = (__expf( a[jp][0] - s) + kEPS) * sc;
                p1.y = (__expf( a[jp][1] - s) + kEPS) * sc;
                p1.z = (__expf( a[jp][2] - s) + kEPS) * sc;
                p1.w = (__expf( a[jp][3] - s) + kEPS) * sc;
                p2.x = (__expf(-a[jp][0] - s) + kEPS) * sc;
                p2.y = (__expf(-a[jp][1] - s) + kEPS) * sc;
                p2.z = (__expf(-a[jp][2] - s) + kEPS) * sc;
                p2.w = (__expf(-a[jp][3] - s) + kEPS) * sc;
                *reinterpret_cast<float4*>(&phis[r * 260 + tx * 4])       = p1;
                *reinterpret_cast<float4*>(&phis[r * 260 + 128 + tx * 4]) = p2;
            }
        }
        __syncthreads();

        // ---- packed accumulate: 3 LDS + 4 splats + 16 FFMA2 per j ----
        #pragma unroll 4
        for (int j = 0; j < 32; j++) {
            float4 ph = *reinterpret_cast<const float4*>(&phis[j * 260 + mi * 4]);   // conflict-free
            ulonglong2 va = *reinterpret_cast<const ulonglong2*>(&vs[j * 68 + di * 8]);      // broadcast
            ulonglong2 vb = *reinterpret_cast<const ulonglong2*>(&vs[j * 68 + di * 8 + 4]);  // broadcast
            ull s0 = pack2(ph.x, ph.x);
            ull s1 = pack2(ph.y, ph.y);
            ull s2 = pack2(ph.z, ph.z);
            ull s3 = pack2(ph.w, ph.w);
            a2[0][0] = fma2(s0, va.x, a2[0][0]); a2[0][1] = fma2(s0, va.y, a2[0][1]);
            a2[0][2] = fma2(s0, vb.x, a2[0][2]); a2[0][3] = fma2(s0, vb.y, a2[0][3]);
            a2[1][0] = fma2(s1, va.x, a2[1][0]); a2[1][1] = fma2(s1, va.y, a2[1][1]);
            a2[1][2] = fma2(s1, vb.x, a2[1][2]); a2[1][3] = fma2(s1, vb.y, a2[1][3]);
            a2[2][0] = fma2(s2, va.x, a2[2][0]); a2[2][1] = fma2(s2, va.y, a2[2][1]);
            a2[2][2] = fma2(s2, vb.x, a2[2][2]); a2[2][3] = fma2(s2, vb.y, a2[2][3]);
            a2[3][0] = fma2(s3, va.x, a2[3][0]); a2[3][1] = fma2(s3, va.y, a2[3][1]);
            a2[3][2] = fma2(s3, vb.x, a2[3][2]); a2[3][3] = fma2(s3, vb.y, a2[3][3]);
            if (di == 0) {
                accn.x += ph.x; accn.y += ph.y; accn.z += ph.z; accn.w += ph.w;
            }
        }
    }

    // ---- unpack and store d-major partials (coalesced float4 over m) ----
    const size_t slab = (size_t)(cx * B_ + b) * DP_;
    #pragma unroll
    for (int dp = 0; dp < 4; dp++) {
        float lo0, hi0, lo1, hi1, lo2, hi2, lo3, hi3;
        unpack2(a2[0][dp], lo0, hi0);
        unpack2(a2[1][dp], lo1, hi1);
        unpack2(a2[2][dp], lo2, hi2);
        unpack2(a2[3][dp], lo3, hi3);
        float4 e = make_float4(lo0, lo1, lo2, lo3);   // d = di*8 + 2*dp
        float4 o = make_float4(hi0, hi1, hi2, hi3);   // d = di*8 + 2*dp + 1
        *reinterpret_cast<float4*>(&g_kvp[(slab + di * 8 + 2 * dp)     * MM2 + mi * 4]) = e;
        *reinterpret_cast<float4*>(&g_kvp[(slab + di * 8 + 2 * dp + 1) * MM2 + mi * 4]) = o;
    }
    if (di == 0)
        *reinterpret_cast<float4*>(&g_kvp[(slab + 64) * MM2 + mi * 4]) = accn;
}

// ======================= Stage 2: reduce partials (float4) =======================
#define KV_N4 (B_ * DP_ * MM2 / 4)   // 33280

__global__ void __launch_bounds__(256) reduce_kv()
{
    int i = blockIdx.x * blockDim.x + threadIdx.x;
    if (i < KV_N4) {
        const float4* src = reinterpret_cast<const float4*>(g_kvp);
        float4 s = make_float4(0.f, 0.f, 0.f, 0.f);
        #pragma unroll
        for (int c = 0; c < KV_CH; c++) {
            float4 v = src[(size_t)c * KV_N4 + i];
            s.x += v.x; s.y += v.y; s.z += v.z; s.w += v.w;
        }
        reinterpret_cast<float4*>(g_kv)[i] = s;
    }
}

// ======================= Stage 3: qkv_fused (phi_q + qkv + normalize) =======================
// grid (T/64, B), block 256. Phase A scalar (R9-identical). Phase B packed:
// thread = 4r x 4c tile, 2 LDS + 4 splats + 8 FFMA2 per m.
#define QF_KVS  0                          // [256][68]  kv[m][d]
#define QF_WT   (256 * 68)                 // [64][132]
#define QF_XS   (QF_WT + 64 * 132)         // [64][68]
#define QF_PHT  (QF_XS + 64 * 68)          // [256][68]  phi^T[m][r]
#define QF_SS   (QF_PHT + 256 * 68)        // [64]
#define QF_NRM  (QF_SS + 64)               // [64]
#define QF_SMEM ((QF_NRM + 64) * 4)        // 190,976 B

__global__ void __launch_bounds__(256) qkv_fused(const float* __restrict__ query,
                                                 const float* __restrict__ omega,
                                                 float* __restrict__ out)
{
    extern __shared__ float sm[];
    float* kvs   = sm + QF_KVS;
    float* wT    = sm + QF_WT;
    float* xs    = sm + QF_XS;
    float* phisT = sm + QF_PHT;
    float* ss    = sm + QF_SS;
    float* norm  = sm + QF_NRM;

    const int b    = blockIdx.y;
    const int t0   = blockIdx.x * 64;
    const int tid  = threadIdx.x;
    const int wid  = tid >> 5;     // 0..7 -> m-16-group
    const int lane = tid & 31;

    // ---- loads: kv (d-major -> [m][d]), omega^T, query tile ----
    {
        const float* kvg = g_kv + (size_t)b * DP_ * MM2;
        #pragma unroll
        for (int it = 0; it < 65; it++) {
            int i = tid + 256 * it;                 // 16640 floats
            int d = i >> 8, mm = i & 255;
            kvs[mm * 68 + d] = kvg[i];
        }
        #pragma unroll
        for (int i = 0; i < 32; i++) {
            int idx = tid + 256 * i;
            wT[(idx & 63) * 132 + (idx >> 6)] = omega[idx];
        }
        const float4* xg = reinterpret_cast<const float4*>(query + ((size_t)b * T_ + t0) * F_);
        #pragma unroll
        for (int i = 0; i < 4; i++) {
            int idx = tid + 256 * i;                // 1024 float4
            int r = idx >> 4, c4 = idx & 15;
            *reinterpret_cast<float4*>(&xs[r * 68 + c4 * 4]) = xg[idx];
        }
    }
    __syncthreads();

    // ---- ss[r] = 0.5 * ||x_r||^2 ----
    if (tid < 64) {
        float p = 0.f;
        #pragma unroll
        for (int f = 0; f < 64; f++) { float v = xs[tid * 68 + f]; p += v * v; }
        ss[tid] = 0.5f * p;
    }
    __syncthreads();

    // ---- phase A: phi_q GEMM (scalar, R9-identical) ----
    {
        float a[2][16];
        #pragma unroll
        for (int jp = 0; jp < 2; jp++)
            #pragma unroll
            for (int c = 0; c < 16; c++) a[jp][c] = 0.f;

        const float* xr0 = &xs[lane * 68];
        const float* xr1 = &xs[(lane + 32) * 68];
        #pragma unroll 4
        for (int f0 = 0; f0 < 64; f0 += 4) {
            float4 xv0 = *reinterpret_cast<const float4*>(&xr0[f0]);
            float4 xv1 = *reinterpret_cast<const float4*>(&xr1[f0]);
            #pragma unroll
            for (int i = 0; i < 4; i++) {
                const float* wr = &wT[(f0 + i) * 132 + wid * 16];
                float4 wa = *reinterpret_cast<const float4*>(wr);
                float4 wb = *reinterpret_cast<const float4*>(wr + 4);
                float4 wc = *reinterpret_cast<const float4*>(wr + 8);
                float4 wd = *reinterpret_cast<const float4*>(wr + 12);
                float x0 = (i == 0) ? xv0.x : (i == 1) ? xv0.y : (i == 2) ? xv0.z : xv0.w;
                float x1 = (i == 0) ? xv1.x : (i == 1) ? xv1.y : (i == 2) ? xv1.z : xv1.w;
                a[0][0]  += x0 * wa.x; a[0][1]  += x0 * wa.y; a[0][2]  += x0 * wa.z; a[0][3]  += x0 * wa.w;
                a[0][4]  += x0 * wb.x; a[0][5]  += x0 * wb.y; a[0][6]  += x0 * wb.z; a[0][7]  += x0 * wb.w;
                a[0][8]  += x0 * wc.x; a[0][9]  += x0 * wc.y; a[0][10] += x0 * wc.z; a[0][11] += x0 * wc.w;
                a[0][12] += x0 * wd.x; a[0][13] += x0 * wd.y; a[0][14] += x0 * wd.z; a[0][15] += x0 * wd.w;
                a[1][0]  += x1 * wa.x; a[1][1]  += x1 * wa.y; a[1][2]  += x1 * wa.z; a[1][3]  += x1 * wa.w;
                a[1][4]  += x1 * wb.x; a[1][5]  += x1 * wb.y; a[1][6]  += x1 * wb.z; a[1][7]  += x1 * wb.w;
                a[1][8]  += x1 * wc.x; a[1][9]  += x1 * wc.y; a[1][10] += x1 * wc.z; a[1][11] += x1 * wc.w;
                a[1][12] += x1 * wd.x; a[1][13] += x1 * wd.y; a[1][14] += x1 * wd.z; a[1][15] += x1 * wd.w;
            }
        }

        // exp + transposed store: phisT[m][r], lane = r -> conflict-free STS.32
        #pragma unroll
        for (int jp = 0; jp < 2; jp++) {
            int r = lane + jp * 32;
            float s = ss[r];
            #pragma unroll
            for (int c = 0; c < 16; c++) {
                int m = wid * 16 + c;
                phisT[m * 68 + r]         = (__expf( a[jp][c] - s) + kEPS) * kSCALE;
                phisT[(128 + m) * 68 + r] = (__expf(-a[jp][c] - s) + kEPS) * kSCALE;
            }
        }
    }
    __syncthreads();

    // ---- phase B: out = phi_q @ kv; packed f32x2, thread = 4 rows x 4 cols ----
    const int rg = tid & 15;       // rows rg*4..rg*4+3
    const int cg = tid >> 4;       // cols cg*4..cg*4+3

    ull a2[4][2];                  // [row][colpair]
    #pragma unroll
    for (int rr = 0; rr < 4; rr++) { a2[rr][0] = 0ULL; a2[rr][1] = 0ULL; }
    float4 anorm = make_float4(0.f, 0.f, 0.f, 0.f);

    #pragma unroll 4
    for (int m = 0; m < MM2; m++) {
        float4 ph = *reinterpret_cast<const float4*>(&phisT[m * 68 + rg * 4]);  // conflict-free
        ulonglong2 kv2 = *reinterpret_cast<const ulonglong2*>(&kvs[m * 68 + cg * 4]);  // ~broadcast
        ull s0 = pack2(ph.x, ph.x);
        ull s1 = pack2(ph.y, ph.y);
        ull s2 = pack2(ph.z, ph.z);
        ull s3 = pack2(ph.w, ph.w);
        a2[0][0] = fma2(s0, kv2.x, a2[0][0]); a2[0][1] = fma2(s0, kv2.y, a2[0][1]);
        a2[1][0] = fma2(s1, kv2.x, a2[1][0]); a2[1][1] = fma2(s1, kv2.y, a2[1][1]);
        a2[2][0] = fma2(s2, kv2.x, a2[2][0]); a2[2][1] = fma2(s2, kv2.y, a2[2][1]);
        a2[3][0] = fma2(s3, kv2.x, a2[3][0]); a2[3][1] = fma2(s3, kv2.y, a2[3][1]);
        if (cg == 0) {
            float kn = kvs[m * 68 + 64];
            anorm.x += ph.x * kn; anorm.y += ph.y * kn;
            anorm.z += ph.z * kn; anorm.w += ph.w * kn;
        }
    }

    if (cg == 0) {
        norm[rg * 4 + 0] = anorm.x;
        norm[rg * 4 + 1] = anorm.y;
        norm[rg * 4 + 2] = anorm.z;
        norm[rg * 4 + 3] = anorm.w;
    }
    __syncthreads();

    #pragma unroll
    for (int rr = 0; rr < 4; rr++) {
        float inv = 1.0f / norm[rg * 4 + rr];
        float c0, c1, c2, c3;
        unpack2(a2[rr][0], c0, c1);
        unpack2(a2[rr][1], c2, c3);
        float4 o = make_float4(c0 * inv, c1 * inv, c2 * inv, c3 * inv);
        *reinterpret_cast<float4*>(out + ((size_t)b * T_ + t0 + rg * 4 + rr) * D_ + cg * 4) = o;
    }
}

// ======================= launch =======================
extern "C" void kernel_launch(void* const* d_in, const int* in_sizes, int n_in,
                              void* d_out, int out_size)
{
    const float* query = (const float*)d_in[0];
    const float* value = (const float*)d_in[1];
    const float* key   = (const float*)d_in[2];
    const float* omega = (const float*)d_in[3];
    float* out = (float*)d_out;

    cudaFuncSetAttribute(kv_fused,  cudaFuncAttributeMaxDynamicSharedMemorySize, KVF_SMEM);
    cudaFuncSetAttribute(qkv_fused, cudaFuncAttributeMaxDynamicSharedMemorySize, QF_SMEM);

    dim3 gkv(KV_CH, B_);
    kv_fused<<<gkv, 512, KVF_SMEM>>>(key, value, omega);
    reduce_kv<<<(KV_N4 + 255) / 256, 256>>>();

    dim3 gq(T_ / 64, B_);
    qkv_fused<<<gq, 256, QF_SMEM>>>(query, omega, out);
}

// round 15
// speedup vs baseline: 1.9148x; 1.1775x over previous
#include <cuda_runtime.h>
#include <math.h>
#include <stdint.h>

#define B_  8
#define T_  8192
#define F_  64
#define M_  128          // omega rows
#define MM2 256          // feature dim = 2*M
#define D_  64
#define DP_ 65           // D + 1 (normalizer column)

#define KV_CH    37      // grid 37*8 = 296 = two waves at 1 CTA/SM
#define KV_ROWS  224     // rows per chunk (37*224 = 8288 >= 8192, tail masked)

constexpr float kEPS   = 1e-9f;
constexpr float kSCALE = 0.0625f;  // 1/sqrt(2*128) = 1/16

// ---------------- device scratch (static, allocation-free) ----------------
// d-major partials: g_kvp[((cx*B+b)*DP + d)*MM2 + m]
__device__ float g_kvp[(size_t)KV_CH * B_ * DP_ * MM2];    // 19.7 MB
__device__ float g_kv [(size_t)B_ * DP_ * MM2];            // 0.53 MB

// ---------------- tf32 helpers (sm_80+ baseline PTX) ----------------
__device__ __forceinline__ float tf32r(float x) {
    uint32_t u;
    asm("cvt.rna.tf32.f32 %0, %1;" : "=r"(u) : "f"(x));
    return __uint_as_float(u);
}
__device__ __forceinline__ void mma_tf32(float* c, const uint32_t* a,
                                         uint32_t b0, uint32_t b1) {
    asm volatile(
        "mma.sync.aligned.m16n8k8.row.col.f32.tf32.tf32.f32 "
        "{%0,%1,%2,%3}, {%4,%5,%6,%7}, {%8,%9}, {%0,%1,%2,%3};"
        : "+f"(c[0]), "+f"(c[1]), "+f"(c[2]), "+f"(c[3])
        : "r"(a[0]), "r"(a[1]), "r"(a[2]), "r"(a[3]), "r"(b0), "r"(b1));
}

// ======================= Stage 1: kv_fused (phi_k scalar + tf32 MMA kv) =======================
// grid (KV_CH, B), block 512, 1 CTA/SM. Per 32-row step:
//   stage K/V (V rounded to tf32) -> phi GEMM (scalar fp32, values rounded
//   to tf32 at store) -> each warp: m16 tile x 9 n8 tiles x 4 k8 chunks MMA.
// C[256m][72d] accumulates in registers across all 7 steps (36 regs/thread).
#define KVF_WT   0                         // [64][132] omega^T padded (fp32)
#define KVF_XS   8448                      // [32][68]  keys (fp32, exact)
#define KVF_VS   10624                     // [32][72]  values (tf32-rounded) + ones col
#define KVF_PHI  12928                     // [32][260] phi (tf32-rounded)
#define KVF_SS   21248                     // [32]
#define KVF_SMEM (21280 * 4)               // 85,120 B

__global__ void __launch_bounds__(512) kv_fused(const float* __restrict__ key,
                                                const float* __restrict__ value,
                                                const float* __restrict__ omega)
{
    extern __shared__ float sm[];
    float* wT   = sm + KVF_WT;
    float* xs   = sm + KVF_XS;
    float* vs   = sm + KVF_VS;
    float* phis = sm + KVF_PHI;
    float* ss   = sm + KVF_SS;

    const int b    = blockIdx.y;
    const int cx   = blockIdx.x;
    const int s0   = cx * KV_ROWS;
    const int tid  = threadIdx.x;
    const int wid  = tid >> 5;
    const int lane = tid & 31;

    // load omega transposed: wT[f][m], stride 132 (one-time)
    #pragma unroll
    for (int i = 0; i < 16; i++) {
        int idx = tid + 512 * i;               // 8192 floats, omega[m][f]
        wT[(idx & 63) * 132 + (idx >> 6)] = omega[idx];
    }
    // ones column (d=64) + zero pad (d=65..71): persists across steps
    if (tid < 256) {
        int s = tid >> 3, c = 64 + (tid & 7);
        vs[s * 72 + c] = ((tid & 7) == 0) ? 1.0f : 0.f;
    }

    // ---- roles ----
    const int tx = lane;           // phi m-quad
    const int lr = tid >> 4;       // staging row 0..31
    const int lc = tid & 15;       // staging float4 col
    const int g  = lane >> 2;      // mma group id
    const int t  = lane & 3;       // mma thread-in-group
    const int mt = wid * 16;       // warp's m-tile base

    // C accumulators: 9 n-tiles x 4 regs (persist across all steps)
    float C[9][4];
    #pragma unroll
    for (int nt = 0; nt < 9; nt++)
        #pragma unroll
        for (int q = 0; q < 4; q++) C[nt][q] = 0.f;

    for (int sb = 0; sb < KV_ROWS; sb += 32) {
        const int sg = s0 + sb;
        __syncthreads();                       // prev MMA reads of phis/vs done

        // ---- stage 32 key + 32 value rows; ss via 16-lane shfl ----
        {
            const int r = sg + lr;
            float4 xv = make_float4(0.f, 0.f, 0.f, 0.f);
            float4 vv = make_float4(0.f, 0.f, 0.f, 0.f);
            if (r < T_) {
                xv = *reinterpret_cast<const float4*>(key   + ((size_t)b * T_ + r) * F_ + lc * 4);
                vv = *reinterpret_cast<const float4*>(value + ((size_t)b * T_ + r) * D_ + lc * 4);
            }
            *reinterpret_cast<float4*>(&xs[lr * 68 + lc * 4]) = xv;
            float4 vt = make_float4(tf32r(vv.x), tf32r(vv.y), tf32r(vv.z), tf32r(vv.w));
            *reinterpret_cast<float4*>(&vs[lr * 72 + lc * 4]) = vt;
            float p = xv.x * xv.x + xv.y * xv.y + xv.z * xv.z + xv.w * xv.w;
            p += __shfl_xor_sync(0xffffffffu, p, 8);
            p += __shfl_xor_sync(0xffffffffu, p, 4);
            p += __shfl_xor_sync(0xffffffffu, p, 2);
            p += __shfl_xor_sync(0xffffffffu, p, 1);
            if (lc == 0) ss[lr] = 0.5f * p;
        }
        __syncthreads();

        // ---- phi GEMM (scalar fp32, R9-identical math): warp wid -> rows wid*2..+1 ----
        {
            float a[2][4];
            #pragma unroll
            for (int jp = 0; jp < 2; jp++)
                #pragma unroll
                for (int c = 0; c < 4; c++) a[jp][c] = 0.f;

            #pragma unroll
            for (int f0 = 0; f0 < 64; f0 += 4) {
                float4 w0 = *reinterpret_cast<const float4*>(&wT[(f0 + 0) * 132 + tx * 4]);
                float4 w1 = *reinterpret_cast<const float4*>(&wT[(f0 + 1) * 132 + tx * 4]);
                float4 w2 = *reinterpret_cast<const float4*>(&wT[(f0 + 2) * 132 + tx * 4]);
                float4 w3 = *reinterpret_cast<const float4*>(&wT[(f0 + 3) * 132 + tx * 4]);
                #pragma unroll
                for (int jp = 0; jp < 2; jp++) {
                    float4 xv = *reinterpret_cast<const float4*>(&xs[(wid * 2 + jp) * 68 + f0]);
                    a[jp][0] += xv.x * w0.x + xv.y * w1.x + xv.z * w2.x + xv.w * w3.x;
                    a[jp][1] += xv.x * w0.y + xv.y * w1.y + xv.z * w2.y + xv.w * w3.y;
                    a[jp][2] += xv.x * w0.z + xv.y * w1.z + xv.z * w2.z + xv.w * w3.z;
                    a[jp][3] += xv.x * w0.w + xv.y * w1.w + xv.z * w2.w + xv.w * w3.w;
                }
            }
            #pragma unroll
            for (int jp = 0; jp < 2; jp++) {
                int r = wid * 2 + jp;
                float s  = ss[r];
                float sc = (sg + r < T_) ? kSCALE : 0.f;
                float4 p1, p2;
                p1.x = tf32r((__expf( a[jp][0] - s) + kEPS) * sc);
                p1.y = tf32r((__expf( a[jp][1] - s) + kEPS) * sc);
                p1.z = tf32r((__expf( a[jp][2] - s) + kEPS) * sc);
                p1.w = tf32r((__expf( a[jp][3] - s) + kEPS) * sc);
                p2.x = tf32r((__expf(-a[jp][0] - s) + kEPS) * sc);
                p2.y = tf32r((__expf(-a[jp][1] - s) + kEPS) * sc);
                p2.z = tf32r((__expf(-a[jp][2] - s) + kEPS) * sc);
                p2.w = tf32r((__expf(-a[jp][3] - s) + kEPS) * sc);
                *reinterpret_cast<float4*>(&phis[r * 260 + tx * 4])       = p1;
                *reinterpret_cast<float4*>(&phis[r * 260 + 128 + tx * 4]) = p2;
            }
        }
        __syncthreads();

        // ---- tf32 MMA accumulate: warp wid -> m-tile mt; C += phi^T x [V|1] ----
        {
            const uint32_t* phU = reinterpret_cast<const uint32_t*>(phis);
            const uint32_t* vsU = reinterpret_cast<const uint32_t*>(vs);
            #pragma unroll
            for (int kc = 0; kc < 4; kc++) {
                const int sA = kc * 8 + t;
                uint32_t A[4];
                A[0] = phU[(sA    ) * 260 + mt + g    ];
                A[1] = phU[(sA    ) * 260 + mt + g + 8];
                A[2] = phU[(sA + 4) * 260 + mt + g    ];
                A[3] = phU[(sA + 4) * 260 + mt + g + 8];
                #pragma unroll
                for (int nt = 0; nt < 9; nt++) {
                    uint32_t b0 = vsU[(sA    ) * 72 + nt * 8 + g];
                    uint32_t b1 = vsU[(sA + 4) * 72 + nt * 8 + g];
                    mma_tf32(C[nt], A, b0, b1);
                }
            }
        }
    }

    // ---- store C fragments -> d-major partials ----
    const size_t slab = (size_t)(cx * B_ + b) * DP_;
    #pragma unroll
    for (int nt = 0; nt < 8; nt++) {
        int d0 = nt * 8 + 2 * t;
        g_kvp[(slab + d0    ) * MM2 + mt + g    ] = C[nt][0];
        g_kvp[(slab + d0 + 1) * MM2 + mt + g    ] = C[nt][1];
        g_kvp[(slab + d0    ) * MM2 + mt + g + 8] = C[nt][2];
        g_kvp[(slab + d0 + 1) * MM2 + mt + g + 8] = C[nt][3];
    }
    if (t == 0) {   // normalizer column d = 64 (n-tile 8, col 64 = 64 + 2*0)
        g_kvp[(slab + 64) * MM2 + mt + g    ] = C[8][0];
        g_kvp[(slab + 64) * MM2 + mt + g + 8] = C[8][2];
    }
}

// ======================= Stage 2: reduce partials (float4) =======================
#define KV_N4 (B_ * DP_ * MM2 / 4)   // 33280

__global__ void __launch_bounds__(256) reduce_kv()
{
    int i = blockIdx.x * blockDim.x + threadIdx.x;
    if (i < KV_N4) {
        const float4* src = reinterpret_cast<const float4*>(g_kvp);
        float4 s = make_float4(0.f, 0.f, 0.f, 0.f);
        #pragma unroll
        for (int c = 0; c < KV_CH; c++) {
            float4 v = src[(size_t)c * KV_N4 + i];
            s.x += v.x; s.y += v.y; s.z += v.z; s.w += v.w;
        }
        reinterpret_cast<float4*>(g_kv)[i] = s;
    }
}

// ======================= Stage 3: qkv_fused (R9 scalar, verified) =======================
#define QF_KVS  0                          // [256][68]  kv[m][d]
#define QF_WT   (256 * 68)                 // [64][132]
#define QF_XS   (QF_WT + 64 * 132)         // [64][68]
#define QF_PHT  (QF_XS + 64 * 68)          // [256][68]  phi^T[m][r]
#define QF_SS   (QF_PHT + 256 * 68)        // [64]
#define QF_NRM  (QF_SS + 64)               // [64]
#define QF_SMEM ((QF_NRM + 64) * 4)        // 190,976 B

__global__ void __launch_bounds__(256) qkv_fused(const float* __restrict__ query,
                                                 const float* __restrict__ omega,
                                                 float* __restrict__ out)
{
    extern __shared__ float sm[];
    float* kvs   = sm + QF_KVS;
    float* wT    = sm + QF_WT;
    float* xs    = sm + QF_XS;
    float* phisT = sm + QF_PHT;
    float* ss    = sm + QF_SS;
    float* norm  = sm + QF_NRM;

    const int b    = blockIdx.y;
    const int t0   = blockIdx.x * 64;
    const int tid  = threadIdx.x;
    const int wid  = tid >> 5;     // 0..7 -> m-16-group
    const int lane = tid & 31;

    // ---- loads: kv (d-major -> [m][d]), omega^T, query tile ----
    {
        const float* kvg = g_kv + (size_t)b * DP_ * MM2;
        #pragma unroll
        for (int it = 0; it < 65; it++) {
            int i = tid + 256 * it;                 // 16640 floats
            int d = i >> 8, mm = i & 255;
            kvs[mm * 68 + d] = kvg[i];
        }
        #pragma unroll
        for (int i = 0; i < 32; i++) {
            int idx = tid + 256 * i;
            wT[(idx & 63) * 132 + (idx >> 6)] = omega[idx];
        }
        const float4* xg = reinterpret_cast<const float4*>(query + ((size_t)b * T_ + t0) * F_);
        #pragma unroll
        for (int i = 0; i < 4; i++) {
            int idx = tid + 256 * i;                // 1024 float4
            int r = idx >> 4, c4 = idx & 15;
            *reinterpret_cast<float4*>(&xs[r * 68 + c4 * 4]) = xg[idx];
        }
    }
    __syncthreads();

    // ---- ss[r] = 0.5 * ||x_r||^2 ----
    if (tid < 64) {
        float p = 0.f;
        #pragma unroll
        for (int f = 0; f < 64; f++) { float v = xs[tid * 68 + f]; p += v * v; }
        ss[tid] = 0.5f * p;
    }
    __syncthreads();

    // ---- phase A: phi_q GEMM (scalar) ----
    {
        float a[2][16];
        #pragma unroll
        for (int jp = 0; jp < 2; jp++)
            #pragma unroll
            for (int c = 0; c < 16; c++) a[jp][c] = 0.f;

        const float* xr0 = &xs[lane * 68];
        const float* xr1 = &xs[(lane + 32) * 68];
        #pragma unroll 4
        for (int f0 = 0; f0 < 64; f0 += 4) {
            float4 xv0 = *reinterpret_cast<const float4*>(&xr0[f0]);
            float4 xv1 = *reinterpret_cast<const float4*>(&xr1[f0]);
            #pragma unroll
            for (int i = 0; i < 4; i++) {
                const float* wr = &wT[(f0 + i) * 132 + wid * 16];
                float4 wa = *reinterpret_cast<const float4*>(wr);
                float4 wb = *reinterpret_cast<const float4*>(wr + 4);
                float4 wc = *reinterpret_cast<const float4*>(wr + 8);
                float4 wd = *reinterpret_cast<const float4*>(wr + 12);
                float x0 = (i == 0) ? xv0.x : (i == 1) ? xv0.y : (i == 2) ? xv0.z : xv0.w;
                float x1 = (i == 0) ? xv1.x : (i == 1) ? xv1.y : (i == 2) ? xv1.z : xv1.w;
                a[0][0]  += x0 * wa.x; a[0][1]  += x0 * wa.y; a[0][2]  += x0 * wa.z; a[0][3]  += x0 * wa.w;
                a[0][4]  += x0 * wb.x; a[0][5]  += x0 * wb.y; a[0][6]  += x0 * wb.z; a[0][7]  += x0 * wb.w;
                a[0][8]  += x0 * wc.x; a[0][9]  += x0 * wc.y; a[0][10] += x0 * wc.z; a[0][11] += x0 * wc.w;
                a[0][12] += x0 * wd.x; a[0][13] += x0 * wd.y; a[0][14] += x0 * wd.z; a[0][15] += x0 * wd.w;
                a[1][0]  += x1 * wa.x; a[1][1]  += x1 * wa.y; a[1][2]  += x1 * wa.z; a[1][3]  += x1 * wa.w;
                a[1][4]  += x1 * wb.x; a[1][5]  += x1 * wb.y; a[1][6]  += x1 * wb.z; a[1][7]  += x1 * wb.w;
                a[1][8]  += x1 * wc.x; a[1][9]  += x1 * wc.y; a[1][10] += x1 * wc.z; a[1][11] += x1 * wc.w;
                a[1][12] += x1 * wd.x; a[1][13] += x1 * wd.y; a[1][14] += x1 * wd.z; a[1][15] += x1 * wd.w;
            }
        }

        // exp + transposed store: phisT[m][r], lane = r -> conflict-free STS.32
        #pragma unroll
        for (int jp = 0; jp < 2; jp++) {
            int r = lane + jp * 32;
            float s = ss[r];
            #pragma unroll
            for (int c = 0; c < 16; c++) {
                int m = wid * 16 + c;
                phisT[m * 68 + r]         = (__expf( a[jp][c] - s) + kEPS) * kSCALE;
                phisT[(128 + m) * 68 + r] = (__expf(-a[jp][c] - s) + kEPS) * kSCALE;
            }
        }
    }
    __syncthreads();

    // ---- phase B: out = phi_q @ kv; thread = 4 rows x 4 cols (scalar float4) ----
    const int rg = tid & 15;       // rows rg*4..rg*4+3
    const int cg = tid >> 4;       // cols cg*4..cg*4+3

    float4 acc[4];
    #pragma unroll
    for (int rr = 0; rr < 4; rr++) acc[rr] = make_float4(0.f, 0.f, 0.f, 0.f);
    float4 anorm = make_float4(0.f, 0.f, 0.f, 0.f);

    #pragma unroll 4
    for (int m = 0; m < MM2; m++) {
        float4 ph = *reinterpret_cast<const float4*>(&phisT[m * 68 + rg * 4]);  // conflict-free
        float4 kv = *reinterpret_cast<const float4*>(&kvs[m * 68 + cg * 4]);    // ~broadcast
        acc[0].x += ph.x * kv.x; acc[0].y += ph.x * kv.y; acc[0].z += ph.x * kv.z; acc[0].w += ph.x * kv.w;
        acc[1].x += ph.y * kv.x; acc[1].y += ph.y * kv.y; acc[1].z += ph.y * kv.z; acc[1].w += ph.y * kv.w;
        acc[2].x += ph.z * kv.x; acc[2].y += ph.z * kv.y; acc[2].z += ph.z * kv.z; acc[2].w += ph.z * kv.w;
        acc[3].x += ph.w * kv.x; acc[3].y += ph.w * kv.y; acc[3].z += ph.w * kv.z; acc[3].w += ph.w * kv.w;
        if (cg == 0) {
            float kn = kvs[m * 68 + 64];
            anorm.x += ph.x * kn; anorm.y += ph.y * kn;
            anorm.z += ph.z * kn; anorm.w += ph.w * kn;
        }
    }

    if (cg == 0) {
        norm[rg * 4 + 0] = anorm.x;
        norm[rg * 4 + 1] = anorm.y;
        norm[rg * 4 + 2] = anorm.z;
        norm[rg * 4 + 3] = anorm.w;
    }
    __syncthreads();

    #pragma unroll
    for (int rr = 0; rr < 4; rr++) {
        float inv = 1.0f / norm[rg * 4 + rr];
        float4 o = make_float4(acc[rr].x * inv, acc[rr].y * inv,
                               acc[rr].z * inv, acc[rr].w * inv);
        *reinterpret_cast<float4*>(out + ((size_t)b * T_ + t0 + rg * 4 + rr) * D_ + cg * 4) = o;
    }
}

// ======================= launch =======================
extern "C" void kernel_launch(void* const* d_in, const int* in_sizes, int n_in,
                              void* d_out, int out_size)
{
    const float* query = (const float*)d_in[0];
    const float* value = (const float*)d_in[1];
    const float* key   = (const float*)d_in[2];
    const float* omega = (const float*)d_in[3];
    float* out = (float*)d_out;

    cudaFuncSetAttribute(kv_fused,  cudaFuncAttributeMaxDynamicSharedMemorySize, KVF_SMEM);
    cudaFuncSetAttribute(qkv_fused, cudaFuncAttributeMaxDynamicSharedMemorySize, QF_SMEM);

    dim3 gkv(KV_CH, B_);
    kv_fused<<<gkv, 512, KVF_SMEM>>>(key, value, omega);
    reduce_kv<<<(KV_N4 + 255) / 256, 256>>>();

    dim3 gq(T_ / 64, B_);
    qkv_fused<<<gq, 256, QF_SMEM>>>(query, omega, out);
}

// round 16
// speedup vs baseline: 2.2824x; 1.1919x over previous
#include <cuda_runtime.h>
#include <math.h>
#include <stdint.h>

#define B_  8
#define T_  8192
#define F_  64
#define M_  128          // omega rows
#define MM2 256          // feature dim = 2*M
#define D_  64
#define DP_ 65           // D + 1 (normalizer column)

#define KV_CH    37      // grid 37*8 = 296
#define KV_ROWS  224     // rows per chunk (37*224 = 8288 >= 8192, tail masked)

constexpr float kEPS   = 1e-9f;
constexpr float kSCALE = 0.0625f;  // 1/sqrt(2*128) = 1/16

// ---------------- device scratch (static, allocation-free) ----------------
// d-major partials: g_kvp[((cx*B+b)*DP + d)*MM2 + m]
__device__ float g_kvp[(size_t)KV_CH * B_ * DP_ * MM2];    // 19.7 MB
__device__ float g_kv [(size_t)B_ * DP_ * MM2];            // 0.53 MB

// ---------------- tf32 helpers (sm_80+ baseline PTX) ----------------
__device__ __forceinline__ float tf32r(float x) {
    uint32_t u;
    asm("cvt.rna.tf32.f32 %0, %1;" : "=r"(u) : "f"(x));
    return __uint_as_float(u);
}
__device__ __forceinline__ void mma_tf32(float* c, const uint32_t* a,
                                         uint32_t b0, uint32_t b1) {
    asm volatile(
        "mma.sync.aligned.m16n8k8.row.col.f32.tf32.tf32.f32 "
        "{%0,%1,%2,%3}, {%4,%5,%6,%7}, {%8,%9}, {%0,%1,%2,%3};"
        : "+f"(c[0]), "+f"(c[1]), "+f"(c[2]), "+f"(c[3])
        : "r"(a[0]), "r"(a[1]), "r"(a[2]), "r"(a[3]), "r"(b0), "r"(b1));
}

// ======================= Stage 1: kv_fused (R15, verified) =======================
#define KVF_WT   0                         // [64][132] omega^T padded (fp32)
#define KVF_XS   8448                      // [32][68]  keys (fp32, exact)
#define KVF_VS   10624                     // [32][72]  values (tf32) + ones col
#define KVF_PHI  12928                     // [32][260] phi (tf32)
#define KVF_SS   21248                     // [32]
#define KVF_SMEM (21280 * 4)               // 85,120 B

__global__ void __launch_bounds__(512) kv_fused(const float* __restrict__ key,
                                                const float* __restrict__ value,
                                                const float* __restrict__ omega)
{
    extern __shared__ float sm[];
    float* wT   = sm + KVF_WT;
    float* xs   = sm + KVF_XS;
    float* vs   = sm + KVF_VS;
    float* phis = sm + KVF_PHI;
    float* ss   = sm + KVF_SS;

    const int b    = blockIdx.y;
    const int cx   = blockIdx.x;
    const int s0   = cx * KV_ROWS;
    const int tid  = threadIdx.x;
    const int wid  = tid >> 5;
    const int lane = tid & 31;

    #pragma unroll
    for (int i = 0; i < 16; i++) {
        int idx = tid + 512 * i;               // 8192 floats, omega[m][f]
        wT[(idx & 63) * 132 + (idx >> 6)] = omega[idx];
    }
    if (tid < 256) {
        int s = tid >> 3, c = 64 + (tid & 7);
        vs[s * 72 + c] = ((tid & 7) == 0) ? 1.0f : 0.f;
    }

    const int tx = lane;
    const int lr = tid >> 4;
    const int lc = tid & 15;
    const int g  = lane >> 2;
    const int t  = lane & 3;
    const int mt = wid * 16;

    float C[9][4];
    #pragma unroll
    for (int nt = 0; nt < 9; nt++)
        #pragma unroll
        for (int q = 0; q < 4; q++) C[nt][q] = 0.f;

    for (int sb = 0; sb < KV_ROWS; sb += 32) {
        const int sg = s0 + sb;
        __syncthreads();

        {
            const int r = sg + lr;
            float4 xv = make_float4(0.f, 0.f, 0.f, 0.f);
            float4 vv = make_float4(0.f, 0.f, 0.f, 0.f);
            if (r < T_) {
                xv = *reinterpret_cast<const float4*>(key   + ((size_t)b * T_ + r) * F_ + lc * 4);
                vv = *reinterpret_cast<const float4*>(value + ((size_t)b * T_ + r) * D_ + lc * 4);
            }
            *reinterpret_cast<float4*>(&xs[lr * 68 + lc * 4]) = xv;
            float4 vt = make_float4(tf32r(vv.x), tf32r(vv.y), tf32r(vv.z), tf32r(vv.w));
            *reinterpret_cast<float4*>(&vs[lr * 72 + lc * 4]) = vt;
            float p = xv.x * xv.x + xv.y * xv.y + xv.z * xv.z + xv.w * xv.w;
            p += __shfl_xor_sync(0xffffffffu, p, 8);
            p += __shfl_xor_sync(0xffffffffu, p, 4);
            p += __shfl_xor_sync(0xffffffffu, p, 2);
            p += __shfl_xor_sync(0xffffffffu, p, 1);
            if (lc == 0) ss[lr] = 0.5f * p;
        }
        __syncthreads();

        {
            float a[2][4];
            #pragma unroll
            for (int jp = 0; jp < 2; jp++)
                #pragma unroll
                for (int c = 0; c < 4; c++) a[jp][c] = 0.f;

            #pragma unroll
            for (int f0 = 0; f0 < 64; f0 += 4) {
                float4 w0 = *reinterpret_cast<const float4*>(&wT[(f0 + 0) * 132 + tx * 4]);
                float4 w1 = *reinterpret_cast<const float4*>(&wT[(f0 + 1) * 132 + tx * 4]);
                float4 w2 = *reinterpret_cast<const float4*>(&wT[(f0 + 2) * 132 + tx * 4]);
                float4 w3 = *reinterpret_cast<const float4*>(&wT[(f0 + 3) * 132 + tx * 4]);
                #pragma unroll
                for (int jp = 0; jp < 2; jp++) {
                    float4 xv = *reinterpret_cast<const float4*>(&xs[(wid * 2 + jp) * 68 + f0]);
                    a[jp][0] += xv.x * w0.x + xv.y * w1.x + xv.z * w2.x + xv.w * w3.x;
                    a[jp][1] += xv.x * w0.y + xv.y * w1.y + xv.z * w2.y + xv.w * w3.y;
                    a[jp][2] += xv.x * w0.z + xv.y * w1.z + xv.z * w2.z + xv.w * w3.z;
                    a[jp][3] += xv.x * w0.w + xv.y * w1.w + xv.z * w2.w + xv.w * w3.w;
                }
            }
            #pragma unroll
            for (int jp = 0; jp < 2; jp++) {
                int r = wid * 2 + jp;
                float s  = ss[r];
                float sc = (sg + r < T_) ? kSCALE : 0.f;
                float4 p1, p2;
                p1.x = tf32r((__expf( a[jp][0] - s) + kEPS) * sc);
                p1.y = tf32r((__expf( a[jp][1] - s) + kEPS) * sc);
                p1.z = tf32r((__expf( a[jp][2] - s) + kEPS) * sc);
                p1.w = tf32r((__expf( a[jp][3] - s) + kEPS) * sc);
                p2.x = tf32r((__expf(-a[jp][0] - s) + kEPS) * sc);
                p2.y = tf32r((__expf(-a[jp][1] - s) + kEPS) * sc);
                p2.z = tf32r((__expf(-a[jp][2] - s) + kEPS) * sc);
                p2.w = tf32r((__expf(-a[jp][3] - s) + kEPS) * sc);
                *reinterpret_cast<float4*>(&phis[r * 260 + tx * 4])       = p1;
                *reinterpret_cast<float4*>(&phis[r * 260 + 128 + tx * 4]) = p2;
            }
        }
        __syncthreads();

        {
            const uint32_t* phU = reinterpret_cast<const uint32_t*>(phis);
            const uint32_t* vsU = reinterpret_cast<const uint32_t*>(vs);
            #pragma unroll
            for (int kc = 0; kc < 4; kc++) {
                const int sA = kc * 8 + t;
                uint32_t A[4];
                A[0] = phU[(sA    ) * 260 + mt + g    ];
                A[1] = phU[(sA    ) * 260 + mt + g + 8];
                A[2] = phU[(sA + 4) * 260 + mt + g    ];
                A[3] = phU[(sA + 4) * 260 + mt + g + 8];
                #pragma unroll
                for (int nt = 0; nt < 9; nt++) {
                    uint32_t b0 = vsU[(sA    ) * 72 + nt * 8 + g];
                    uint32_t b1 = vsU[(sA + 4) * 72 + nt * 8 + g];
                    mma_tf32(C[nt], A, b0, b1);
                }
            }
        }
    }

    const size_t slab = (size_t)(cx * B_ + b) * DP_;
    #pragma unroll
    for (int nt = 0; nt < 8; nt++) {
        int d0 = nt * 8 + 2 * t;
        g_kvp[(slab + d0    ) * MM2 + mt + g    ] = C[nt][0];
        g_kvp[(slab + d0 + 1) * MM2 + mt + g    ] = C[nt][1];
        g_kvp[(slab + d0    ) * MM2 + mt + g + 8] = C[nt][2];
        g_kvp[(slab + d0 + 1) * MM2 + mt + g + 8] = C[nt][3];
    }
    if (t == 0) {
        g_kvp[(slab + 64) * MM2 + mt + g    ] = C[8][0];
        g_kvp[(slab + 64) * MM2 + mt + g + 8] = C[8][2];
    }
}

// ======================= Stage 2: reduce partials (float4) =======================
#define KV_N4 (B_ * DP_ * MM2 / 4)   // 33280

__global__ void __launch_bounds__(256) reduce_kv()
{
    int i = blockIdx.x * blockDim.x + threadIdx.x;
    if (i < KV_N4) {
        const float4* src = reinterpret_cast<const float4*>(g_kvp);
        float4 s = make_float4(0.f, 0.f, 0.f, 0.f);
        #pragma unroll
        for (int c = 0; c < KV_CH; c++) {
            float4 v = src[(size_t)c * KV_N4 + i];
            s.x += v.x; s.y += v.y; s.z += v.z; s.w += v.w;
        }
        reinterpret_cast<float4*>(g_kv)[i] = s;
    }
}

// ======================= Stage 3: qkv_fused (phi_q scalar + tf32 MMA) =======================
// grid (T/64, B), block 256. Phase A: scalar phi (tf32-rounded at store,
// stride 72). Phase B: warp = (m-tile wid&3, n-half wid>>2); C = phisT^T @ kv
// via m16n8k8 tf32 MMA; normalizer = n-tile 8 col 64.
#define QF_KVS  0                          // [256][72]  kv[m][d] tf32, cols 65..71 = 0
#define QF_WT   (256 * 72)                 // [64][132]
#define QF_XS   (QF_WT + 64 * 132)         // [64][68]
#define QF_PHT  (QF_XS + 64 * 68)          // [256][72]  phi^T[m][r] tf32
#define QF_NRM  (QF_PHT + 256 * 72)        // [64]
#define QF_SS   (QF_NRM + 64)              // [64]
#define QF_SMEM ((QF_SS + 64) * 4)         // 199,680 B

__global__ void __launch_bounds__(256) qkv_fused(const float* __restrict__ query,
                                                 const float* __restrict__ omega,
                                                 float* __restrict__ out)
{
    extern __shared__ float sm[];
    float* kvs   = sm + QF_KVS;
    float* wT    = sm + QF_WT;
    float* xs    = sm + QF_XS;
    float* phisT = sm + QF_PHT;
    float* norm  = sm + QF_NRM;
    float* ss    = sm + QF_SS;

    const int b    = blockIdx.y;
    const int t0   = blockIdx.x * 64;
    const int tid  = threadIdx.x;
    const int wid  = tid >> 5;     // 0..7
    const int lane = tid & 31;

    // ---- loads: kv (d-major -> [m][d] tf32, stride 72), omega^T, query ----
    {
        const float* kvg = g_kv + (size_t)b * DP_ * MM2;
        #pragma unroll
        for (int it = 0; it < 65; it++) {
            int i = tid + 256 * it;                 // 16640 floats
            int d = i >> 8, mm = i & 255;
            kvs[mm * 72 + d] = tf32r(kvg[i]);
        }
        // zero pad cols 65..71
        for (int i = tid; i < 256 * 7; i += 256) {
            int mm = i / 7, dd = 65 + (i - mm * 7);
            kvs[mm * 72 + dd] = 0.f;
        }
        #pragma unroll
        for (int i = 0; i < 32; i++) {
            int idx = tid + 256 * i;
            wT[(idx & 63) * 132 + (idx >> 6)] = omega[idx];
        }
        const float4* xg = reinterpret_cast<const float4*>(query + ((size_t)b * T_ + t0) * F_);
        #pragma unroll
        for (int i = 0; i < 4; i++) {
            int idx = tid + 256 * i;                // 1024 float4
            int r = idx >> 4, c4 = idx & 15;
            *reinterpret_cast<float4*>(&xs[r * 68 + c4 * 4]) = xg[idx];
        }
    }
    __syncthreads();

    // ---- ss[r] = 0.5 * ||x_r||^2 ----
    if (tid < 64) {
        float p = 0.f;
        #pragma unroll
        for (int f = 0; f < 64; f++) { float v = xs[tid * 68 + f]; p += v * v; }
        ss[tid] = 0.5f * p;
    }
    __syncthreads();

    // ---- phase A: phi_q GEMM (scalar); tf32-rounded transposed store ----
    {
        float a[2][16];
        #pragma unroll
        for (int jp = 0; jp < 2; jp++)
            #pragma unroll
            for (int c = 0; c < 16; c++) a[jp][c] = 0.f;

        const float* xr0 = &xs[lane * 68];
        const float* xr1 = &xs[(lane + 32) * 68];
        #pragma unroll 4
        for (int f0 = 0; f0 < 64; f0 += 4) {
            float4 xv0 = *reinterpret_cast<const float4*>(&xr0[f0]);
            float4 xv1 = *reinterpret_cast<const float4*>(&xr1[f0]);
            #pragma unroll
            for (int i = 0; i < 4; i++) {
                const float* wr = &wT[(f0 + i) * 132 + wid * 16];
                float4 wa = *reinterpret_cast<const float4*>(wr);
                float4 wb = *reinterpret_cast<const float4*>(wr + 4);
                float4 wc = *reinterpret_cast<const float4*>(wr + 8);
                float4 wd = *reinterpret_cast<const float4*>(wr + 12);
                float x0 = (i == 0) ? xv0.x : (i == 1) ? xv0.y : (i == 2) ? xv0.z : xv0.w;
                float x1 = (i == 0) ? xv1.x : (i == 1) ? xv1.y : (i == 2) ? xv1.z : xv1.w;
                a[0][0]  += x0 * wa.x; a[0][1]  += x0 * wa.y; a[0][2]  += x0 * wa.z; a[0][3]  += x0 * wa.w;
                a[0][4]  += x0 * wb.x; a[0][5]  += x0 * wb.y; a[0][6]  += x0 * wb.z; a[0][7]  += x0 * wb.w;
                a[0][8]  += x0 * wc.x; a[0][9]  += x0 * wc.y; a[0][10] += x0 * wc.z; a[0][11] += x0 * wc.w;
                a[0][12] += x0 * wd.x; a[0][13] += x0 * wd.y; a[0][14] += x0 * wd.z; a[0][15] += x0 * wd.w;
                a[1][0]  += x1 * wa.x; a[1][1]  += x1 * wa.y; a[1][2]  += x1 * wa.z; a[1][3]  += x1 * wa.w;
                a[1][4]  += x1 * wb.x; a[1][5]  += x1 * wb.y; a[1][6]  += x1 * wb.z; a[1][7]  += x1 * wb.w;
                a[1][8]  += x1 * wc.x; a[1][9]  += x1 * wc.y; a[1][10] += x1 * wc.z; a[1][11] += x1 * wc.w;
                a[1][12] += x1 * wd.x; a[1][13] += x1 * wd.y; a[1][14] += x1 * wd.z; a[1][15] += x1 * wd.w;
            }
        }

        #pragma unroll
        for (int jp = 0; jp < 2; jp++) {
            int r = lane + jp * 32;
            float s = ss[r];
            #pragma unroll
            for (int c = 0; c < 16; c++) {
                int m = wid * 16 + c;
                phisT[m * 72 + r]         = tf32r((__expf( a[jp][c] - s) + kEPS) * kSCALE);
                phisT[(128 + m) * 72 + r] = tf32r((__expf(-a[jp][c] - s) + kEPS) * kSCALE);
            }
        }
    }
    __syncthreads();

    // ---- phase B: tf32 MMA; warp = (m-tile, n-half) ----
    const int g    = lane >> 2;
    const int t    = lane & 3;
    const int wp   = wid & 3;        // m-tile -> rows wp*16..+15
    const int half = wid >> 2;       // 0: n-tiles 0..4, 1: n-tiles 5..8
    const int r0   = wp * 16;
    const int ntb  = half ? 5 : 0;
    const int ntc  = half ? 4 : 5;

    float C[5][4];
    #pragma unroll
    for (int nt = 0; nt < 5; nt++)
        #pragma unroll
        for (int q = 0; q < 4; q++) C[nt][q] = 0.f;

    {
        const uint32_t* phU = reinterpret_cast<const uint32_t*>(phisT);
        const uint32_t* kvU = reinterpret_cast<const uint32_t*>(kvs);
        #pragma unroll 4
        for (int kc = 0; kc < 32; kc++) {
            const int k0 = kc * 8 + t;
            uint32_t A[4];
            A[0] = phU[(k0    ) * 72 + r0 + g    ];
            A[1] = phU[(k0    ) * 72 + r0 + g + 8];
            A[2] = phU[(k0 + 4) * 72 + r0 + g    ];
            A[3] = phU[(k0 + 4) * 72 + r0 + g + 8];
            #pragma unroll
            for (int nn = 0; nn < 5; nn++) {
                if (nn < ntc) {
                    int nt = ntb + nn;
                    uint32_t b0 = kvU[(k0    ) * 72 + nt * 8 + g];
                    uint32_t b1 = kvU[(k0 + 4) * 72 + nt * 8 + g];
                    mma_tf32(C[nn], A, b0, b1);
                }
            }
        }
    }

    // normalizer: half==1, local tile 3 (= nt 8), col 64 -> t==0 holds c0/c2
    if (half == 1 && t == 0) {
        norm[r0 + g    ] = C[3][0];
        norm[r0 + g + 8] = C[3][2];
    }
    __syncthreads();

    // ---- normalize + store: half0 -> cols 0..39, half1 -> cols 40..63 ----
    const float inv0 = 1.0f / norm[r0 + g];
    const float inv1 = 1.0f / norm[r0 + g + 8];
    const int nout = half ? 3 : 5;          // half1: nt 5,6,7 only (nt8 = normalizer)
    #pragma unroll
    for (int nn = 0; nn < 5; nn++) {
        if (nn < nout) {
            int c0 = (ntb + nn) * 8 + 2 * t;
            float* o0 = out + ((size_t)b * T_ + t0 + r0 + g    ) * D_ + c0;
            float* o1 = out + ((size_t)b * T_ + t0 + r0 + g + 8) * D_ + c0;
            o0[0] = C[nn][0] * inv0;
            o0[1] = C[nn][1] * inv0;
            o1[0] = C[nn][2] * inv1;
            o1[1] = C[nn][3] * inv1;
        }
    }
}

// ======================= launch =======================
extern "C" void kernel_launch(void* const* d_in, const int* in_sizes, int n_in,
                              void* d_out, int out_size)
{
    const float* query = (const float*)d_in[0];
    const float* value = (const float*)d_in[1];
    const float* key   = (const float*)d_in[2];
    const float* omega = (const float*)d_in[3];
    float* out = (float*)d_out;

    cudaFuncSetAttribute(kv_fused,  cudaFuncAttributeMaxDynamicSharedMemorySize, KVF_SMEM);
    cudaFuncSetAttribute(qkv_fused, cudaFuncAttributeMaxDynamicSharedMemorySize, QF_SMEM);

    dim3 gkv(KV_CH, B_);
    kv_fused<<<gkv, 512, KVF_SMEM>>>(key, value, omega);
    reduce_kv<<<(KV_N4 + 255) / 256, 256>>>();

    dim3 gq(T_ / 64, B_);
    qkv_fused<<<gq, 256, QF_SMEM>>>(query, omega, out);
}